// round 1
// baseline (speedup 1.0000x reference)
#include <cuda_runtime.h>
#include <math.h>

#define NN 8192
#define DD 256
#define BM 128
#define BN 128
#define BK 32
#define TM 8
#define TN 8

// Scratch for row squared-norms (no cudaMalloc allowed).
__device__ float g_sq[NN];

// One warp per row: sq[i] = sum_k x[i,k]^2
__global__ void sq_kernel(const float* __restrict__ x) {
    int warp = (blockIdx.x * blockDim.x + threadIdx.x) >> 5;
    int lane = threadIdx.x & 31;
    if (warp >= NN) return;
    const float4* xr = reinterpret_cast<const float4*>(x + (size_t)warp * DD);
    float4 a = xr[lane];
    float4 b = xr[lane + 32];
    float s = a.x*a.x + a.y*a.y + a.z*a.z + a.w*a.w
            + b.x*b.x + b.y*b.y + b.z*b.z + b.w*b.w;
    #pragma unroll
    for (int o = 16; o; o >>= 1) s += __shfl_xor_sync(0xffffffffu, s, o);
    if (lane == 0) g_sq[warp] = s;
}

// Tiled fp32 GEMM (dot_ij = x_i . x_j) with fused distance/sigmoid epilogue.
// out[i,j] = 1 - sigmoid((sqrt(max(sq_i + sq_j - 2*dot, 1e-12)) + thr) * t)
__global__ void __launch_bounds__(256) dist_kernel(
    const float* __restrict__ x,
    const float* __restrict__ thr_p,
    const float* __restrict__ t_p,
    float* __restrict__ out)
{
    __shared__ float As[BK][BM + 4];
    __shared__ float Bs[BK][BN + 4];

    const int tid  = threadIdx.x;
    const int tn   = tid & 15;   // 0..15 -> column micro-tile
    const int tmw  = tid >> 4;   // 0..15 -> row micro-tile
    const int row0 = blockIdx.y * BM;
    const int col0 = blockIdx.x * BN;

    // Loader mapping: 8 lanes cover one row's BK=32 floats (coalesced float4),
    // 32 rows per pass, 4 passes -> 128 rows.
    const int lkc = tid & 7;     // which float4 along k
    const int lm  = tid >> 3;    // 0..31 row-in-tile

    const float* xa = x + (size_t)(row0 + lm) * DD + lkc * 4;
    const float* xb = x + (size_t)(col0 + lm) * DD + lkc * 4;

    float acc[TM][TN];
    #pragma unroll
    for (int i = 0; i < TM; i++)
        #pragma unroll
        for (int j = 0; j < TN; j++) acc[i][j] = 0.f;

    for (int k0 = 0; k0 < DD; k0 += BK) {
        #pragma unroll
        for (int r = 0; r < 4; r++) {
            float4 va = *reinterpret_cast<const float4*>(xa + (size_t)(r * 32) * DD + k0);
            float4 vb = *reinterpret_cast<const float4*>(xb + (size_t)(r * 32) * DD + k0);
            const int m  = lm + r * 32;
            const int kk = lkc * 4;
            As[kk + 0][m] = va.x; As[kk + 1][m] = va.y;
            As[kk + 2][m] = va.z; As[kk + 3][m] = va.w;
            Bs[kk + 0][m] = vb.x; Bs[kk + 1][m] = vb.y;
            Bs[kk + 2][m] = vb.z; Bs[kk + 3][m] = vb.w;
        }
        __syncthreads();

        #pragma unroll
        for (int k = 0; k < BK; k++) {
            float a[TM], b[TN];
            #pragma unroll
            for (int i = 0; i < TM; i += 4) {
                float4 v = *reinterpret_cast<const float4*>(&As[k][tmw * TM + i]);
                a[i] = v.x; a[i + 1] = v.y; a[i + 2] = v.z; a[i + 3] = v.w;
            }
            #pragma unroll
            for (int j = 0; j < TN; j += 4) {
                float4 v = *reinterpret_cast<const float4*>(&Bs[k][tn * TN + j]);
                b[j] = v.x; b[j + 1] = v.y; b[j + 2] = v.z; b[j + 3] = v.w;
            }
            #pragma unroll
            for (int i = 0; i < TM; i++)
                #pragma unroll
                for (int j = 0; j < TN; j++)
                    acc[i][j] = fmaf(a[i], b[j], acc[i][j]);
        }
        __syncthreads();
    }

    const float thr = *thr_p;
    const float tt  = *t_p;

    float sa[TM], sb[TN];
    #pragma unroll
    for (int i = 0; i < TM; i++) sa[i] = g_sq[row0 + tmw * TM + i];
    #pragma unroll
    for (int j = 0; j < TN; j++) sb[j] = g_sq[col0 + tn * TN + j];

    #pragma unroll
    for (int i = 0; i < TM; i++) {
        float4 o4[2];
        float* ov = reinterpret_cast<float*>(o4);
        #pragma unroll
        for (int j = 0; j < TN; j++) {
            float d2   = sa[i] + sb[j] - 2.f * acc[i][j];
            float dist = sqrtf(fmaxf(d2, 1e-12f));
            float diff = (dist + thr) * tt;
            // Written exactly like the reference: 1 - sigmoid(diff).
            // For diff > ~17.3 this saturates to exactly 0.0f, matching ref bitwise.
            float s = 1.f / (1.f + __expf(-diff));
            ov[j] = 1.f - s;
        }
        float4* dst = reinterpret_cast<float4*>(
            out + (size_t)(row0 + tmw * TM + i) * NN + (col0 + tn * TN));
        dst[0] = o4[0];
        dst[1] = o4[1];
    }
}

extern "C" void kernel_launch(void* const* d_in, const int* in_sizes, int n_in,
                              void* d_out, int out_size) {
    const float* x   = (const float*)d_in[0];
    const float* thr = (const float*)d_in[1];
    const float* t   = (const float*)d_in[2];
    float* out = (float*)d_out;

    sq_kernel<<<NN / 8, 256>>>(x);

    dim3 grid(NN / BN, NN / BM);
    dist_kernel<<<grid, 256>>>(x, thr, t, out);
}

// round 3
// speedup vs baseline: 2.6583x; 2.6583x over previous
#include <cuda_runtime.h>
#include <cuda_bf16.h>
#include <math.h>
#include <cstdint>

#define NN 8192
#define DD 256

// ---------------- device scratch (no cudaMalloc allowed) ----------------
__device__ float g_sq[NN];
__device__ __nv_bfloat16 g_xb[(size_t)NN * DD];    // 4 MB bf16 copy of x   [row][k]
__device__ __nv_bfloat16 g_xbT[(size_t)DD * NN];   // 4 MB bf16 x^T         [k][row]

__device__ __forceinline__ uint32_t smem_u32(const void* p) {
    uint32_t a;
    asm("{ .reg .u64 t; cvta.to.shared.u64 t, %1; cvt.u32.u64 %0, t; }" : "=r"(a) : "l"(p));
    return a;
}

// ---------------- prep: sq norms + fp32 -> bf16 row-major copy ----------------
__global__ void prep_kernel(const float* __restrict__ x) {
    int warp = (blockIdx.x * blockDim.x + threadIdx.x) >> 5;
    int lane = threadIdx.x & 31;
    if (warp >= NN) return;
    const float4* xr = reinterpret_cast<const float4*>(x + (size_t)warp * DD);
    float4 a = xr[lane * 2];
    float4 b = xr[lane * 2 + 1];
    float s = a.x*a.x + a.y*a.y + a.z*a.z + a.w*a.w
            + b.x*b.x + b.y*b.y + b.z*b.z + b.w*b.w;
    #pragma unroll
    for (int o = 16; o; o >>= 1) s += __shfl_xor_sync(0xffffffffu, s, o);
    if (lane == 0) g_sq[warp] = s;

    __nv_bfloat162 p0 = __float22bfloat162_rn(make_float2(a.x, a.y));
    __nv_bfloat162 p1 = __float22bfloat162_rn(make_float2(a.z, a.w));
    __nv_bfloat162 p2 = __float22bfloat162_rn(make_float2(b.x, b.y));
    __nv_bfloat162 p3 = __float22bfloat162_rn(make_float2(b.z, b.w));
    uint4 v;
    v.x = *reinterpret_cast<uint32_t*>(&p0);
    v.y = *reinterpret_cast<uint32_t*>(&p1);
    v.z = *reinterpret_cast<uint32_t*>(&p2);
    v.w = *reinterpret_cast<uint32_t*>(&p3);
    reinterpret_cast<uint4*>(g_xb + (size_t)warp * DD)[lane] = v;
}

// ---------------- transpose: x [N][D] fp32 -> g_xbT [D][N] bf16 ----------------
__global__ void transpose_kernel(const float* __restrict__ x) {
    __shared__ float s[32][33];
    const int i0 = blockIdx.x * 32;       // row block
    const int k0 = blockIdx.y * 32;       // col block
    const int tx = threadIdx.x, ty = threadIdx.y;   // (32, 8)
    #pragma unroll
    for (int it = 0; it < 4; it++)
        s[ty + 8 * it][tx] = x[(size_t)(i0 + ty + 8 * it) * DD + k0 + tx];
    __syncthreads();
    #pragma unroll
    for (int it = 0; it < 4; it++) {
        int k = k0 + ty + 8 * it;
        g_xbT[(size_t)k * NN + i0 + tx] = __float2bfloat16(s[tx][ty + 8 * it]);
    }
}

// ---------------- bf16 mma.sync GEMM + fused epilogue ----------------
// CTA tile 128x128, full K=256 resident in smem.
// A: [128 rows][256 bf16], row stride 528B (512 + 16 pad) -> 4-bank rotation.
// B: [256 k-rows][128 bf16], row stride 272B (256 + 16 pad).
#define A_STRIDE 528
#define B_STRIDE 272
#define SB_OFF   (128 * A_STRIDE)                 // 67584
#define SM_TOTAL (SB_OFF + 256 * B_STRIDE)        // 137216

__device__ __forceinline__ void ldsm4(uint32_t* r, uint32_t addr) {
    asm volatile("ldmatrix.sync.aligned.m8n8.x4.shared.b16 {%0,%1,%2,%3}, [%4];"
                 : "=r"(r[0]), "=r"(r[1]), "=r"(r[2]), "=r"(r[3]) : "r"(addr));
}
__device__ __forceinline__ void ldsm2t(uint32_t* r, uint32_t addr) {
    asm volatile("ldmatrix.sync.aligned.m8n8.x2.trans.shared.b16 {%0,%1}, [%2];"
                 : "=r"(r[0]), "=r"(r[1]) : "r"(addr));
}
__device__ __forceinline__ void mma16816(float* c, const uint32_t* a, const uint32_t* b) {
    asm volatile("mma.sync.aligned.m16n8k16.row.col.f32.bf16.bf16.f32 "
                 "{%0,%1,%2,%3}, {%4,%5,%6,%7}, {%8,%9}, {%0,%1,%2,%3};"
                 : "+f"(c[0]), "+f"(c[1]), "+f"(c[2]), "+f"(c[3])
                 : "r"(a[0]), "r"(a[1]), "r"(a[2]), "r"(a[3]), "r"(b[0]), "r"(b[1]));
}

__device__ __forceinline__ float epi(float dot, float sa, float sb,
                                     float thr, float tt, float cut2) {
    float d2 = sa + sb - 2.f * dot;
    if (d2 > cut2) return 0.f;                    // 1-sigmoid saturates to exactly 0.0f
    float dist = sqrtf(fmaxf(d2, 1e-12f));
    return 1.f - 1.f / (1.f + __expf(-(dist + thr) * tt));
}

__global__ void __launch_bounds__(256, 1) gemm_kernel(
    const float* __restrict__ thr_p, const float* __restrict__ t_p,
    float* __restrict__ out)
{
    extern __shared__ char smem[];
    const uint32_t sbase = smem_u32(smem);
    const int tid = threadIdx.x, wid = tid >> 5, lane = tid & 31;
    const int row0 = blockIdx.y * 128;
    const int col0 = blockIdx.x * 128;

    // ---- load A tile (row-major, coalesced) ----
    {
        const uint4* srcA = reinterpret_cast<const uint4*>(g_xb + (size_t)row0 * DD);
        #pragma unroll
        for (int i = 0; i < 16; i++) {
            int idx = tid + i * 256;              // 0..4095
            int r = idx >> 5, u = idx & 31;       // row, 16B unit along k
            *reinterpret_cast<uint4*>(smem + r * A_STRIDE + u * 16) = srcA[idx];
        }
        // ---- load B tile (k-major from transposed copy, coalesced) ----
        #pragma unroll
        for (int i = 0; i < 16; i++) {
            int idx = tid + i * 256;              // 0..4095
            int k = idx >> 4, u = idx & 15;       // k-row, 16B unit along n
            uint4 v = *reinterpret_cast<const uint4*>(
                reinterpret_cast<const char*>(g_xbT + (size_t)k * NN + col0) + u * 16);
            *reinterpret_cast<uint4*>(smem + SB_OFF + k * B_STRIDE + u * 16) = v;
        }
    }
    __syncthreads();

    // ---- warp layout: 2 (m) x 4 (n); warp tile 64 x 32 ----
    const int wm = wid >> 2, wn = wid & 3;

    float c[4][4][4];
    #pragma unroll
    for (int mi = 0; mi < 4; mi++)
        #pragma unroll
        for (int ni = 0; ni < 4; ni++)
            #pragma unroll
            for (int q = 0; q < 4; q++) c[mi][ni][q] = 0.f;

    // ldmatrix per-lane bases
    const uint32_t aB = sbase + (uint32_t)(wm * 64 + (lane & 15)) * A_STRIDE
                      + ((uint32_t)(lane >> 4) << 4);            // +16B for k+8 half
    const uint32_t bB = sbase + SB_OFF + (uint32_t)(lane & 15) * B_STRIDE
                      + (uint32_t)wn * 64;                       // n offset in bytes

    #pragma unroll
    for (int ks = 0; ks < 16; ks++) {
        uint32_t a[4][4];
        #pragma unroll
        for (int mi = 0; mi < 4; mi++)
            ldsm4(a[mi], aB + ks * 32 + mi * (16 * A_STRIDE));
        uint32_t b[4][2];
        #pragma unroll
        for (int ni = 0; ni < 4; ni++)
            ldsm2t(b[ni], bB + ks * (16 * B_STRIDE) + ni * 16);
        #pragma unroll
        for (int mi = 0; mi < 4; mi++)
            #pragma unroll
            for (int ni = 0; ni < 4; ni++)
                mma16816(c[mi][ni], a[mi], b[ni]);
    }

    // ---- fused epilogue straight from registers ----
    const float thr = *thr_p, tt = *t_p;
    float cut2 = 3.0e38f;                          // tt <= 0: never shortcut
    if (tt > 0.f) { float cd = 17.0f / tt - thr; cut2 = (cd > 0.f) ? cd * cd : -1.0f; }

    const int gr = lane >> 2, gc = lane & 3;
    #pragma unroll
    for (int mi = 0; mi < 4; mi++) {
        const int r0 = row0 + wm * 64 + mi * 16 + gr;
        const float sa0 = g_sq[r0], sa1 = g_sq[r0 + 8];
        #pragma unroll
        for (int ni = 0; ni < 4; ni++) {
            const int col = col0 + wn * 32 + ni * 8 + gc * 2;
            const float sb0 = g_sq[col], sb1 = g_sq[col + 1];
            float2 v0, v1;
            v0.x = epi(c[mi][ni][0], sa0, sb0, thr, tt, cut2);
            v0.y = epi(c[mi][ni][1], sa0, sb1, thr, tt, cut2);
            v1.x = epi(c[mi][ni][2], sa1, sb0, thr, tt, cut2);
            v1.y = epi(c[mi][ni][3], sa1, sb1, thr, tt, cut2);
            *reinterpret_cast<float2*>(out + (size_t)r0 * NN + col) = v0;
            *reinterpret_cast<float2*>(out + (size_t)(r0 + 8) * NN + col) = v1;
        }
    }
}

// ---------------- fp32 diagonal-block fixup (identical arithmetic to R1) ----------------
#define BM 128
#define BK 32
#define TMt 8
#define TNt 8
__global__ void __launch_bounds__(256) diag_kernel(
    const float* __restrict__ x,
    const float* __restrict__ thr_p,
    const float* __restrict__ t_p,
    float* __restrict__ out)
{
    __shared__ float As[BK][BM + 4];
    __shared__ float Bs[BK][BM + 4];

    const int tid = threadIdx.x;
    const int tn = tid & 15;
    const int tmw = tid >> 4;
    const int row0 = blockIdx.x * BM;
    const int col0 = row0;

    const int lkc = tid & 7;
    const int lm = tid >> 3;
    const float* xa = x + (size_t)(row0 + lm) * DD + lkc * 4;

    float acc[TMt][TNt];
    #pragma unroll
    for (int i = 0; i < TMt; i++)
        #pragma unroll
        for (int j = 0; j < TNt; j++) acc[i][j] = 0.f;

    for (int k0 = 0; k0 < DD; k0 += BK) {
        #pragma unroll
        for (int r = 0; r < 4; r++) {
            float4 va = *reinterpret_cast<const float4*>(xa + (size_t)(r * 32) * DD + k0);
            const int m = lm + r * 32;
            const int kk = lkc * 4;
            As[kk + 0][m] = va.x; As[kk + 1][m] = va.y;
            As[kk + 2][m] = va.z; As[kk + 3][m] = va.w;
            Bs[kk + 0][m] = va.x; Bs[kk + 1][m] = va.y;
            Bs[kk + 2][m] = va.z; Bs[kk + 3][m] = va.w;
        }
        __syncthreads();
        #pragma unroll
        for (int k = 0; k < BK; k++) {
            float a[TMt], b[TNt];
            #pragma unroll
            for (int i = 0; i < TMt; i += 4) {
                float4 v = *reinterpret_cast<const float4*>(&As[k][tmw * TMt + i]);
                a[i] = v.x; a[i + 1] = v.y; a[i + 2] = v.z; a[i + 3] = v.w;
            }
            #pragma unroll
            for (int j = 0; j < TNt; j += 4) {
                float4 v = *reinterpret_cast<const float4*>(&Bs[k][tn * TNt + j]);
                b[j] = v.x; b[j + 1] = v.y; b[j + 2] = v.z; b[j + 3] = v.w;
            }
            #pragma unroll
            for (int i = 0; i < TMt; i++)
                #pragma unroll
                for (int j = 0; j < TNt; j++)
                    acc[i][j] = fmaf(a[i], b[j], acc[i][j]);
        }
        __syncthreads();
    }

    const float thr = *thr_p;
    const float tt = *t_p;
    float sa[TMt], sb2[TNt];
    #pragma unroll
    for (int i = 0; i < TMt; i++) sa[i] = g_sq[row0 + tmw * TMt + i];
    #pragma unroll
    for (int j = 0; j < TNt; j++) sb2[j] = g_sq[col0 + tn * TNt + j];

    #pragma unroll
    for (int i = 0; i < TMt; i++) {
        float4 o4[2];
        float* ov = reinterpret_cast<float*>(o4);
        #pragma unroll
        for (int j = 0; j < TNt; j++) {
            float d2 = sa[i] + sb2[j] - 2.f * acc[i][j];
            float dist = sqrtf(fmaxf(d2, 1e-12f));
            float diff = (dist + thr) * tt;
            float s = 1.f / (1.f + __expf(-diff));
            ov[j] = 1.f - s;
        }
        float4* dst = reinterpret_cast<float4*>(
            out + (size_t)(row0 + tmw * TMt + i) * NN + (col0 + tn * TNt));
        dst[0] = o4[0];
        dst[1] = o4[1];
    }
}

extern "C" void kernel_launch(void* const* d_in, const int* in_sizes, int n_in,
                              void* d_out, int out_size) {
    const float* x   = (const float*)d_in[0];
    const float* thr = (const float*)d_in[1];
    const float* t   = (const float*)d_in[2];
    float* out = (float*)d_out;

    cudaFuncSetAttribute(gemm_kernel, cudaFuncAttributeMaxDynamicSharedMemorySize, SM_TOTAL);

    prep_kernel<<<NN / 8, 256>>>(x);                        // sq norms + bf16 rows
    dim3 tgrid(NN / 32, DD / 32);
    transpose_kernel<<<tgrid, dim3(32, 8)>>>(x);            // bf16 x^T

    dim3 grid(NN / 128, NN / 128);                          // 64 x 64 = 4096 tiles
    gemm_kernel<<<grid, 256, SM_TOTAL>>>(thr, t, out);

    diag_kernel<<<NN / 128, 256>>>(x, thr, t, out);         // fp32 diagonal overwrite
}

// round 5
// speedup vs baseline: 4.6356x; 1.7438x over previous
#include <cuda_runtime.h>
#include <cuda_bf16.h>
#include <math.h>
#include <cstdint>

#define NN 8192
#define DD 256

// ---------------- device scratch (no cudaMalloc allowed) ----------------
__device__ float g_sq[NN];
__device__ __nv_bfloat16 g_xb[(size_t)NN * DD];    // 4 MB bf16 copy of x   [row][k]
__device__ __nv_bfloat16 g_xbT[(size_t)DD * NN];   // 4 MB bf16 x^T         [k][row]

__device__ __forceinline__ uint32_t smem_u32(const void* p) {
    uint32_t a;
    asm("{ .reg .u64 t; cvta.to.shared.u64 t, %1; cvt.u32.u64 %0, t; }" : "=r"(a) : "l"(p));
    return a;
}

// ---------------- prep: sq norms + fp32 -> bf16 row-major copy ----------------
__global__ void prep_kernel(const float* __restrict__ x) {
    int warp = (blockIdx.x * blockDim.x + threadIdx.x) >> 5;
    int lane = threadIdx.x & 31;
    if (warp >= NN) return;
    const float4* xr = reinterpret_cast<const float4*>(x + (size_t)warp * DD);
    float4 a = xr[lane * 2];
    float4 b = xr[lane * 2 + 1];
    float s = a.x*a.x + a.y*a.y + a.z*a.z + a.w*a.w
            + b.x*b.x + b.y*b.y + b.z*b.z + b.w*b.w;
    #pragma unroll
    for (int o = 16; o; o >>= 1) s += __shfl_xor_sync(0xffffffffu, s, o);
    if (lane == 0) g_sq[warp] = s;

    __nv_bfloat162 p0 = __float22bfloat162_rn(make_float2(a.x, a.y));
    __nv_bfloat162 p1 = __float22bfloat162_rn(make_float2(a.z, a.w));
    __nv_bfloat162 p2 = __float22bfloat162_rn(make_float2(b.x, b.y));
    __nv_bfloat162 p3 = __float22bfloat162_rn(make_float2(b.z, b.w));
    uint4 v;
    v.x = *reinterpret_cast<uint32_t*>(&p0);
    v.y = *reinterpret_cast<uint32_t*>(&p1);
    v.z = *reinterpret_cast<uint32_t*>(&p2);
    v.w = *reinterpret_cast<uint32_t*>(&p3);
    reinterpret_cast<uint4*>(g_xb + (size_t)warp * DD)[lane] = v;
}

// ---------------- transpose: x [N][D] fp32 -> g_xbT [D][N] bf16 ----------------
__global__ void transpose_kernel(const float* __restrict__ x) {
    __shared__ float s[32][33];
    const int i0 = blockIdx.x * 32;
    const int k0 = blockIdx.y * 32;
    const int tx = threadIdx.x, ty = threadIdx.y;   // (32, 8)
    #pragma unroll
    for (int it = 0; it < 4; it++)
        s[ty + 8 * it][tx] = x[(size_t)(i0 + ty + 8 * it) * DD + k0 + tx];
    __syncthreads();
    #pragma unroll
    for (int it = 0; it < 4; it++) {
        int k = k0 + ty + 8 * it;
        g_xbT[(size_t)k * NN + i0 + tx] = __float2bfloat16(s[tx][ty + 8 * it]);
    }
}

// ---------------- bf16 mma.sync GEMM, upper-triangle tiles + mirrored store ----------------
#define A_STRIDE 528
#define B_STRIDE 272
#define SB_OFF   (128 * A_STRIDE)                 // 67584
#define SM_TOTAL (SB_OFF + 256 * B_STRIDE)        // 137216
#define RS_STRIDE 132                              // staging: float[128][132]

__device__ __forceinline__ void ldsm4(uint32_t* r, uint32_t addr) {
    asm volatile("ldmatrix.sync.aligned.m8n8.x4.shared.b16 {%0,%1,%2,%3}, [%4];"
                 : "=r"(r[0]), "=r"(r[1]), "=r"(r[2]), "=r"(r[3]) : "r"(addr));
}
__device__ __forceinline__ void ldsm2t(uint32_t* r, uint32_t addr) {
    asm volatile("ldmatrix.sync.aligned.m8n8.x2.trans.shared.b16 {%0,%1}, [%2];"
                 : "=r"(r[0]), "=r"(r[1]) : "r"(addr));
}
__device__ __forceinline__ void mma16816(float* c, const uint32_t* a, const uint32_t* b) {
    asm volatile("mma.sync.aligned.m16n8k16.row.col.f32.bf16.bf16.f32 "
                 "{%0,%1,%2,%3}, {%4,%5,%6,%7}, {%8,%9}, {%0,%1,%2,%3};"
                 : "+f"(c[0]), "+f"(c[1]), "+f"(c[2]), "+f"(c[3])
                 : "r"(a[0]), "r"(a[1]), "r"(a[2]), "r"(a[3]), "r"(b[0]), "r"(b[1]));
}

__device__ __forceinline__ float epi(float dot, float sa, float sb,
                                     float thr, float tt, float cut2) {
    float d2 = sa + sb - 2.f * dot;
    if (d2 > cut2) return 0.f;                    // 1-sigmoid saturates to exactly 0.0f
    float dist = sqrtf(fmaxf(d2, 1e-12f));
    return 1.f - 1.f / (1.f + __expf(-(dist + thr) * tt));
}

#define NTILE 64          // 8192 / 128
#define NPAIRS 2080       // 64*65/2 upper-triangle tiles (incl. diagonal)

__global__ void __launch_bounds__(256, 1) gemm_kernel(
    const float* __restrict__ thr_p, const float* __restrict__ t_p,
    float* __restrict__ out)
{
    extern __shared__ char smem[];
    const uint32_t sbase = smem_u32(smem);
    const int tid = threadIdx.x, wid = tid >> 5, lane = tid & 31;

    // triangular decode: block i -> (by, bx) with bx >= by
    int bi = blockIdx.x;
    int by = (int)(64.5f - sqrtf(64.5f * 64.5f - 2.0f * (float)bi));
    #define FROW(b) ((b) * NTILE - ((b) * ((b) - 1)) / 2)
    while (FROW(by + 1) <= bi) by++;
    while (FROW(by) > bi) by--;
    const int bx = by + (bi - FROW(by));
    const int row0 = by * 128;
    const int col0 = bx * 128;

    // ---- load A tile (rows, row-major) and B tile (k-major) ----
    {
        const uint4* srcA = reinterpret_cast<const uint4*>(g_xb + (size_t)row0 * DD);
        #pragma unroll
        for (int i = 0; i < 16; i++) {
            int idx = tid + i * 256;
            int r = idx >> 5, u = idx & 31;
            *reinterpret_cast<uint4*>(smem + r * A_STRIDE + u * 16) = srcA[idx];
        }
        #pragma unroll
        for (int i = 0; i < 16; i++) {
            int idx = tid + i * 256;
            int k = idx >> 4, u = idx & 15;
            uint4 v = *reinterpret_cast<const uint4*>(
                reinterpret_cast<const char*>(g_xbT + (size_t)k * NN + col0) + u * 16);
            *reinterpret_cast<uint4*>(smem + SB_OFF + k * B_STRIDE + u * 16) = v;
        }
    }
    __syncthreads();

    const int wm = wid >> 2, wn = wid & 3;

    float c[4][4][4];
    #pragma unroll
    for (int mi = 0; mi < 4; mi++)
        #pragma unroll
        for (int ni = 0; ni < 4; ni++)
            #pragma unroll
            for (int q = 0; q < 4; q++) c[mi][ni][q] = 0.f;

    const uint32_t aB = sbase + (uint32_t)(wm * 64 + (lane & 15)) * A_STRIDE
                      + ((uint32_t)(lane >> 4) << 4);
    const uint32_t bB = sbase + SB_OFF + (uint32_t)(lane & 15) * B_STRIDE
                      + (uint32_t)wn * 64;

    #pragma unroll
    for (int ks = 0; ks < 16; ks++) {
        uint32_t a[4][4];
        #pragma unroll
        for (int mi = 0; mi < 4; mi++)
            ldsm4(a[mi], aB + ks * 32 + mi * (16 * A_STRIDE));
        uint32_t b[4][2];
        #pragma unroll
        for (int ni = 0; ni < 4; ni++)
            ldsm2t(b[ni], bB + ks * (16 * B_STRIDE) + ni * 16);
        #pragma unroll
        for (int mi = 0; mi < 4; mi++)
            #pragma unroll
            for (int ni = 0; ni < 4; ni++)
                mma16816(c[mi][ni], a[mi], b[ni]);
    }
    __syncthreads();   // all smem reads done; safe to reuse smem as staging

    // ---- epilogue: direct store + transposed staging for the mirror tile ----
    const float thr = *thr_p, tt = *t_p;
    float cut2 = 3.0e38f;
    if (tt > 0.f) { float cd = 17.0f / tt - thr; cut2 = (cd > 0.f) ? cd * cd : -1.0f; }

    float* rs = reinterpret_cast<float*>(smem);     // [128 cols][RS_STRIDE]
    const bool mirror = (bx > by);
    const int gr = lane >> 2, gc = lane & 3;

    #pragma unroll
    for (int mi = 0; mi < 4; mi++) {
        const int lr0 = wm * 64 + mi * 16 + gr;
        const int r0 = row0 + lr0;
        const float sa0 = g_sq[r0], sa1 = g_sq[r0 + 8];
        #pragma unroll
        for (int ni = 0; ni < 4; ni++) {
            const int lc = wn * 32 + ni * 8 + gc * 2;
            const int col = col0 + lc;
            const float sb0 = g_sq[col], sb1 = g_sq[col + 1];
            float2 v0, v1;
            v0.x = epi(c[mi][ni][0], sa0, sb0, thr, tt, cut2);
            v0.y = epi(c[mi][ni][1], sa0, sb1, thr, tt, cut2);
            v1.x = epi(c[mi][ni][2], sa1, sb0, thr, tt, cut2);
            v1.y = epi(c[mi][ni][3], sa1, sb1, thr, tt, cut2);
            *reinterpret_cast<float2*>(out + (size_t)r0 * NN + col) = v0;
            *reinterpret_cast<float2*>(out + (size_t)(r0 + 8) * NN + col) = v1;
            if (mirror) {
                rs[(lc)     * RS_STRIDE + lr0]     = v0.x;
                rs[(lc + 1) * RS_STRIDE + lr0]     = v0.y;
                rs[(lc)     * RS_STRIDE + lr0 + 8] = v1.x;
                rs[(lc + 1) * RS_STRIDE + lr0 + 8] = v1.y;
            }
        }
    }

    if (mirror) {
        __syncthreads();
        #pragma unroll
        for (int it = 0; it < 16; it++) {
            int idx = tid + it * 256;
            int j = idx >> 5, u = idx & 31;
            float4 v = *reinterpret_cast<const float4*>(&rs[j * RS_STRIDE + 4 * u]);
            *reinterpret_cast<float4*>(out + (size_t)(col0 + j) * NN + row0 + 4 * u) = v;
        }
    }
}

// ---------------- diagonal elements: fp32 sequential-FMA dot (ref-correlated) ----------------
// Reproduces R1's accumulation ordering: strictly sequential FMA chain over k,
// then d2 = (sq+sq) - 2*dot.  Empirically tracks the reference's fp32
// cancellation residual (rel_err ~9e-4 vs 3.4e-3 for an analytic-zero diagonal).
__global__ void diagfix_kernel(const float* __restrict__ x,
                               const float* __restrict__ thr_p,
                               const float* __restrict__ t_p,
                               float* __restrict__ out) {
    int i = blockIdx.x * 128 + threadIdx.x;
    if (i >= NN) return;
    const float4* xr = reinterpret_cast<const float4*>(x + (size_t)i * DD);
    float dot = 0.f;
    #pragma unroll
    for (int u = 0; u < DD / 4; u++) {
        float4 v = xr[u];
        dot = fmaf(v.x, v.x, dot);
        dot = fmaf(v.y, v.y, dot);
        dot = fmaf(v.z, v.z, dot);
        dot = fmaf(v.w, v.w, dot);
    }
    float sq = g_sq[i];
    float d2 = fmaf(-2.f, dot, sq + sq);
    float dist = sqrtf(fmaxf(d2, 1e-12f));
    float thr = *thr_p, tt = *t_p;
    float v = 1.f - 1.f / (1.f + __expf(-(dist + thr) * tt));
    out[(size_t)i * NN + i] = v;
}

extern "C" void kernel_launch(void* const* d_in, const int* in_sizes, int n_in,
                              void* d_out, int out_size) {
    const float* x   = (const float*)d_in[0];
    const float* thr = (const float*)d_in[1];
    const float* t   = (const float*)d_in[2];
    float* out = (float*)d_out;

    cudaFuncSetAttribute(gemm_kernel, cudaFuncAttributeMaxDynamicSharedMemorySize, SM_TOTAL);

    prep_kernel<<<NN / 8, 256>>>(x);                 // sq norms + bf16 rows
    dim3 tgrid(NN / 32, DD / 32);
    transpose_kernel<<<tgrid, dim3(32, 8)>>>(x);     // bf16 x^T

    gemm_kernel<<<NPAIRS, 256, SM_TOTAL>>>(thr, t, out);   // upper triangle + mirror

    diagfix_kernel<<<NN / 128, 128>>>(x, thr, t, out);     // fp32 diag elements
}

// round 6
// speedup vs baseline: 4.7524x; 1.0252x over previous
#include <cuda_runtime.h>
#include <cuda_bf16.h>
#include <math.h>
#include <cstdint>

#define NN 8192
#define DD 256

// ---------------- device scratch (no cudaMalloc allowed) ----------------
__device__ float g_sq[NN];
__device__ __nv_bfloat16 g_xb[(size_t)NN * DD];    // 4 MB bf16 copy of x   [row][k]

__device__ __forceinline__ uint32_t smem_u32(const void* p) {
    uint32_t a;
    asm("{ .reg .u64 t; cvta.to.shared.u64 t, %1; cvt.u32.u64 %0, t; }" : "=r"(a) : "l"(p));
    return a;
}

#define CP_ASYNC16(dst, src) \
    asm volatile("cp.async.cg.shared.global [%0], [%1], 16;" :: "r"(dst), "l"(src))
#define CP_COMMIT() asm volatile("cp.async.commit_group;" ::: "memory")
#define CP_WAIT(n)  asm volatile("cp.async.wait_group %0;" :: "n"(n) : "memory")

// ---------------- prep: sq norms + fp32 -> bf16 row-major copy ----------------
__global__ void prep_kernel(const float* __restrict__ x) {
    int warp = (blockIdx.x * blockDim.x + threadIdx.x) >> 5;
    int lane = threadIdx.x & 31;
    if (warp >= NN) return;
    const float4* xr = reinterpret_cast<const float4*>(x + (size_t)warp * DD);
    float4 a = xr[lane * 2];
    float4 b = xr[lane * 2 + 1];
    float s = a.x*a.x + a.y*a.y + a.z*a.z + a.w*a.w
            + b.x*b.x + b.y*b.y + b.z*b.z + b.w*b.w;
    #pragma unroll
    for (int o = 16; o; o >>= 1) s += __shfl_xor_sync(0xffffffffu, s, o);
    if (lane == 0) g_sq[warp] = s;

    __nv_bfloat162 p0 = __float22bfloat162_rn(make_float2(a.x, a.y));
    __nv_bfloat162 p1 = __float22bfloat162_rn(make_float2(a.z, a.w));
    __nv_bfloat162 p2 = __float22bfloat162_rn(make_float2(b.x, b.y));
    __nv_bfloat162 p3 = __float22bfloat162_rn(make_float2(b.z, b.w));
    uint4 v;
    v.x = *reinterpret_cast<uint32_t*>(&p0);
    v.y = *reinterpret_cast<uint32_t*>(&p1);
    v.z = *reinterpret_cast<uint32_t*>(&p2);
    v.w = *reinterpret_cast<uint32_t*>(&p3);
    reinterpret_cast<uint4*>(g_xb + (size_t)warp * DD)[lane] = v;
}

// ---------------- bf16 mma.sync GEMM, upper-triangle tiles + mirrored store ----------------
// A and B tiles both row-major [128 rows][256 bf16], row stride 528B (4-bank rotation).
#define A_STRIDE 528
#define SB_OFF   (128 * A_STRIDE)                 // 67584
#define SM_TOTAL (2 * SB_OFF)                     // 135168
#define RS_STRIDE 132                              // staging: float[128][132] = 67584 B

__device__ __forceinline__ void ldsm4(uint32_t* r, uint32_t addr) {
    asm volatile("ldmatrix.sync.aligned.m8n8.x4.shared.b16 {%0,%1,%2,%3}, [%4];"
                 : "=r"(r[0]), "=r"(r[1]), "=r"(r[2]), "=r"(r[3]) : "r"(addr));
}
__device__ __forceinline__ void mma16816(float* c, const uint32_t* a, const uint32_t* b) {
    asm volatile("mma.sync.aligned.m16n8k16.row.col.f32.bf16.bf16.f32 "
                 "{%0,%1,%2,%3}, {%4,%5,%6,%7}, {%8,%9}, {%0,%1,%2,%3};"
                 : "+f"(c[0]), "+f"(c[1]), "+f"(c[2]), "+f"(c[3])
                 : "r"(a[0]), "r"(a[1]), "r"(a[2]), "r"(a[3]), "r"(b[0]), "r"(b[1]));
}

__device__ __forceinline__ float epi(float dot, float sa, float sb,
                                     float thr, float tt, float cut2) {
    float d2 = sa + sb - 2.f * dot;
    if (d2 > cut2) return 0.f;                    // 1-sigmoid saturates to exactly 0.0f
    float dist = sqrtf(fmaxf(d2, 1e-12f));
    return 1.f - 1.f / (1.f + __expf(-(dist + thr) * tt));
}

#define NTILE 64          // 8192 / 128
#define NPAIRS 2080       // 64*65/2 upper-triangle tiles (incl. diagonal)

__global__ void __launch_bounds__(256, 1) gemm_kernel(
    const float* __restrict__ x,
    const float* __restrict__ thr_p, const float* __restrict__ t_p,
    float* __restrict__ out)
{
    extern __shared__ char smem[];
    const uint32_t sbase = smem_u32(smem);
    const int tid = threadIdx.x, wid = tid >> 5, lane = tid & 31;

    // triangular decode: block i -> (by, bx) with bx >= by
    int bi = blockIdx.x;
    int by = (int)(64.5f - sqrtf(64.5f * 64.5f - 2.0f * (float)bi));
    #define FROW(b) ((b) * NTILE - ((b) * ((b) - 1)) / 2)
    while (FROW(by + 1) <= bi) by++;
    while (FROW(by) > bi) by--;
    const int bx = by + (bi - FROW(by));
    const int row0 = by * 128;
    const int col0 = bx * 128;
    const bool dup = (bx == by);

    // ---- async tile loads, two K-chunks of 128 ----
    const char* gA = reinterpret_cast<const char*>(g_xb) + (size_t)row0 * 512;
    const char* gB = reinterpret_cast<const char*>(g_xb) + (size_t)col0 * 512;
    #pragma unroll
    for (int c = 0; c < 2; c++) {
        #pragma unroll
        for (int i = 0; i < 8; i++) {
            int idx = tid + i * 256;          // 0..2047
            int r = idx >> 4, u = idx & 15;
            uint32_t off = (uint32_t)(r * A_STRIDE + c * 256 + u * 16);
            size_t   goff = (size_t)r * 512 + c * 256 + u * 16;
            CP_ASYNC16(sbase + off, gA + goff);
            if (!dup) CP_ASYNC16(sbase + SB_OFF + off, gB + goff);
        }
        CP_COMMIT();
    }

    const int wm = wid >> 2, wn = wid & 3;

    float c[4][4][4];
    #pragma unroll
    for (int mi = 0; mi < 4; mi++)
        #pragma unroll
        for (int ni = 0; ni < 4; ni++)
            #pragma unroll
            for (int q = 0; q < 4; q++) c[mi][ni][q] = 0.f;

    // A frag base: lanes 0-15 -> rows (wm*64 + mi*16 + lane&15), lanes 16-31 -> +16B (k+8)
    const uint32_t aB = sbase + (uint32_t)(wm * 64 + (lane & 15)) * A_STRIDE
                      + ((uint32_t)(lane >> 4) << 4);
    // B frag base (non-trans x4, two n8-tiles per load):
    // lane groups: (l&7) row-in-8, (l>>3)&1 -> +16B (k+8), (l>>4) -> +8 n-rows
    const uint32_t bOffBase = dup ? 0u : (uint32_t)SB_OFF;
    const uint32_t bB = sbase + bOffBase
                      + (uint32_t)(wn * 32 + (lane & 7) + ((lane >> 4) << 3)) * A_STRIDE
                      + (uint32_t)(((lane >> 3) & 1) << 4);

    CP_WAIT(1);            // chunk 0 resident
    __syncthreads();

    #pragma unroll
    for (int half = 0; half < 2; half++) {
        if (half == 1) {
            CP_WAIT(0);    // chunk 1 resident
            __syncthreads();
        }
        #pragma unroll
        for (int k8 = 0; k8 < 8; k8++) {
            const int ks = half * 8 + k8;
            uint32_t a[4][4];
            #pragma unroll
            for (int mi = 0; mi < 4; mi++)
                ldsm4(a[mi], aB + ks * 32 + mi * (16 * A_STRIDE));
            uint32_t b[2][4];   // b[p] covers n8-tiles 2p, 2p+1: regs {t0k0,t0k8,t1k0,t1k8}
            #pragma unroll
            for (int p = 0; p < 2; p++)
                ldsm4(b[p], bB + ks * 32 + p * (16 * A_STRIDE));
            #pragma unroll
            for (int mi = 0; mi < 4; mi++)
                #pragma unroll
                for (int ni = 0; ni < 4; ni++)
                    mma16816(c[mi][ni], a[mi], &b[ni >> 1][(ni & 1) * 2]);
        }
    }
    __syncthreads();   // all smem reads done; safe to reuse smem as staging

    // ---- epilogue: direct store + transposed staging for the mirror tile ----
    const float thr = *thr_p, tt = *t_p;
    float cut2 = 3.0e38f;
    if (tt > 0.f) { float cd = 17.0f / tt - thr; cut2 = (cd > 0.f) ? cd * cd : -1.0f; }

    float* rs = reinterpret_cast<float*>(smem);     // [128 cols][RS_STRIDE]
    const bool mirror = !dup;
    const int gr = lane >> 2, gc = lane & 3;

    #pragma unroll
    for (int mi = 0; mi < 4; mi++) {
        const int lr0 = wm * 64 + mi * 16 + gr;
        const int r0 = row0 + lr0;
        const float sa0 = g_sq[r0], sa1 = g_sq[r0 + 8];
        #pragma unroll
        for (int ni = 0; ni < 4; ni++) {
            const int lc = wn * 32 + ni * 8 + gc * 2;
            const int col = col0 + lc;
            const float sb0 = g_sq[col], sb1 = g_sq[col + 1];
            float2 v0, v1;
            v0.x = epi(c[mi][ni][0], sa0, sb0, thr, tt, cut2);
            v0.y = epi(c[mi][ni][1], sa0, sb1, thr, tt, cut2);
            v1.x = epi(c[mi][ni][2], sa1, sb0, thr, tt, cut2);
            v1.y = epi(c[mi][ni][3], sa1, sb1, thr, tt, cut2);
            *reinterpret_cast<float2*>(out + (size_t)r0 * NN + col) = v0;
            *reinterpret_cast<float2*>(out + (size_t)(r0 + 8) * NN + col) = v1;
            if (mirror) {
                rs[(lc)     * RS_STRIDE + lr0]     = v0.x;
                rs[(lc + 1) * RS_STRIDE + lr0]     = v0.y;
                rs[(lc)     * RS_STRIDE + lr0 + 8] = v1.x;
                rs[(lc + 1) * RS_STRIDE + lr0 + 8] = v1.y;
            }
        }
    }

    if (mirror) {
        __syncthreads();
        #pragma unroll
        for (int it = 0; it < 16; it++) {
            int idx = tid + it * 256;
            int j = idx >> 5, u = idx & 31;
            float4 v = *reinterpret_cast<const float4*>(&rs[j * RS_STRIDE + 4 * u]);
            *reinterpret_cast<float4*>(out + (size_t)(col0 + j) * NN + row0 + 4 * u) = v;
        }
    } else {
        // ---- fused diagonal-element fixup (verbatim R5 arithmetic) ----
        __syncthreads();   // order after this CTA's epilogue stores to the diagonal
        if (tid < 128) {
            const int i = row0 + tid;
            const float4* xr = reinterpret_cast<const float4*>(x + (size_t)i * DD);
            float dot = 0.f;
            #pragma unroll
            for (int u = 0; u < DD / 4; u++) {
                float4 v = xr[u];
                dot = fmaf(v.x, v.x, dot);
                dot = fmaf(v.y, v.y, dot);
                dot = fmaf(v.z, v.z, dot);
                dot = fmaf(v.w, v.w, dot);
            }
            float sq = g_sq[i];
            float d2 = fmaf(-2.f, dot, sq + sq);
            float dist = sqrtf(fmaxf(d2, 1e-12f));
            float v = 1.f - 1.f / (1.f + __expf(-(dist + thr) * tt));
            out[(size_t)i * NN + i] = v;
        }
    }
}

extern "C" void kernel_launch(void* const* d_in, const int* in_sizes, int n_in,
                              void* d_out, int out_size) {
    const float* x   = (const float*)d_in[0];
    const float* thr = (const float*)d_in[1];
    const float* t   = (const float*)d_in[2];
    float* out = (float*)d_out;

    cudaFuncSetAttribute(gemm_kernel, cudaFuncAttributeMaxDynamicSharedMemorySize, SM_TOTAL);

    prep_kernel<<<NN / 8, 256>>>(x);                       // sq norms + bf16 rows
    gemm_kernel<<<NPAIRS, 256, SM_TOTAL>>>(x, thr, t, out);  // triangle + mirror + diag
}

// round 7
// speedup vs baseline: 6.0136x; 1.2654x over previous
#include <cuda_runtime.h>
#include <cuda_bf16.h>
#include <math.h>
#include <cstdint>

#define NN 8192
#define DD 256

// ---------------- device scratch (no cudaMalloc allowed) ----------------
__device__ float g_sq[NN];
__device__ __nv_bfloat16 g_xb[(size_t)NN * DD];    // 4 MB bf16 copy of x   [row][k]

__device__ __forceinline__ uint32_t smem_u32(const void* p) {
    uint32_t a;
    asm("{ .reg .u64 t; cvta.to.shared.u64 t, %1; cvt.u32.u64 %0, t; }" : "=r"(a) : "l"(p));
    return a;
}

#define CP_ASYNC16(dst, src) \
    asm volatile("cp.async.cg.shared.global [%0], [%1], 16;" :: "r"(dst), "l"(src))
#define CP_COMMIT() asm volatile("cp.async.commit_group;" ::: "memory")
#define CP_WAIT(n)  asm volatile("cp.async.wait_group %0;" :: "n"(n) : "memory")

// ---------------- prep: sq norms + fp32 -> bf16 row-major copy ----------------
__global__ void prep_kernel(const float* __restrict__ x) {
    int warp = (blockIdx.x * blockDim.x + threadIdx.x) >> 5;
    int lane = threadIdx.x & 31;
    if (warp >= NN) return;
    const float4* xr = reinterpret_cast<const float4*>(x + (size_t)warp * DD);
    float4 a = xr[lane * 2];
    float4 b = xr[lane * 2 + 1];
    float s = a.x*a.x + a.y*a.y + a.z*a.z + a.w*a.w
            + b.x*b.x + b.y*b.y + b.z*b.z + b.w*b.w;
    #pragma unroll
    for (int o = 16; o; o >>= 1) s += __shfl_xor_sync(0xffffffffu, s, o);
    if (lane == 0) g_sq[warp] = s;

    __nv_bfloat162 p0 = __float22bfloat162_rn(make_float2(a.x, a.y));
    __nv_bfloat162 p1 = __float22bfloat162_rn(make_float2(a.z, a.w));
    __nv_bfloat162 p2 = __float22bfloat162_rn(make_float2(b.x, b.y));
    __nv_bfloat162 p3 = __float22bfloat162_rn(make_float2(b.z, b.w));
    uint4 v;
    v.x = *reinterpret_cast<uint32_t*>(&p0);
    v.y = *reinterpret_cast<uint32_t*>(&p1);
    v.z = *reinterpret_cast<uint32_t*>(&p2);
    v.w = *reinterpret_cast<uint32_t*>(&p3);
    reinterpret_cast<uint4*>(g_xb + (size_t)warp * DD)[lane] = v;
}

// ---------------- bf16 mma.sync GEMM, upper-triangle tiles + mirrored store ----------------
// A and B tiles both row-major [128 rows][256 bf16], row stride 528B (4-bank rotation).
#define A_STRIDE 528
#define SB_OFF   (128 * A_STRIDE)                 // 67584
#define SM_TOTAL (2 * SB_OFF)                     // 135168
#define RS_STRIDE 132                              // staging: float[128][132] = 67584 B
#define NT 512                                     // threads per CTA (16 warps)

__device__ __forceinline__ void ldsm4(uint32_t* r, uint32_t addr) {
    asm volatile("ldmatrix.sync.aligned.m8n8.x4.shared.b16 {%0,%1,%2,%3}, [%4];"
                 : "=r"(r[0]), "=r"(r[1]), "=r"(r[2]), "=r"(r[3]) : "r"(addr));
}
__device__ __forceinline__ void mma16816(float* c, const uint32_t* a, const uint32_t* b) {
    asm volatile("mma.sync.aligned.m16n8k16.row.col.f32.bf16.bf16.f32 "
                 "{%0,%1,%2,%3}, {%4,%5,%6,%7}, {%8,%9}, {%0,%1,%2,%3};"
                 : "+f"(c[0]), "+f"(c[1]), "+f"(c[2]), "+f"(c[3])
                 : "r"(a[0]), "r"(a[1]), "r"(a[2]), "r"(a[3]), "r"(b[0]), "r"(b[1]));
}

__device__ __forceinline__ float epi(float dot, float sa, float sb,
                                     float thr, float tt, float cut2) {
    float d2 = sa + sb - 2.f * dot;
    if (d2 > cut2) return 0.f;                    // 1-sigmoid saturates to exactly 0.0f
    float dist = sqrtf(fmaxf(d2, 1e-12f));
    return 1.f - 1.f / (1.f + __expf(-(dist + thr) * tt));
}

#define NTILE 64          // 8192 / 128
#define NPAIRS 2080       // 64*65/2 upper-triangle tiles (incl. diagonal)

__global__ void __launch_bounds__(NT, 1) gemm_kernel(
    const float* __restrict__ x,
    const float* __restrict__ thr_p, const float* __restrict__ t_p,
    float* __restrict__ out)
{
    extern __shared__ char smem[];
    const uint32_t sbase = smem_u32(smem);
    const int tid = threadIdx.x, wid = tid >> 5, lane = tid & 31;

    // triangular decode: block i -> (by, bx) with bx >= by
    int bi = blockIdx.x;
    int by = (int)(64.5f - sqrtf(64.5f * 64.5f - 2.0f * (float)bi));
    #define FROW(b) ((b) * NTILE - ((b) * ((b) - 1)) / 2)
    while (FROW(by + 1) <= bi) by++;
    while (FROW(by) > bi) by--;
    const int bx = by + (bi - FROW(by));
    const int row0 = by * 128;
    const int col0 = bx * 128;
    const bool dup = (bx == by);

    // ---- async tile loads, two K-chunks of 128 (512 threads) ----
    const char* gA = reinterpret_cast<const char*>(g_xb) + (size_t)row0 * 512;
    const char* gB = reinterpret_cast<const char*>(g_xb) + (size_t)col0 * 512;
    #pragma unroll
    for (int c = 0; c < 2; c++) {
        #pragma unroll
        for (int i = 0; i < 4; i++) {
            int idx = tid + i * NT;           // 0..2047
            int r = idx >> 4, u = idx & 15;
            uint32_t off = (uint32_t)(r * A_STRIDE + c * 256 + u * 16);
            size_t   goff = (size_t)r * 512 + c * 256 + u * 16;
            CP_ASYNC16(sbase + off, gA + goff);
            if (!dup) CP_ASYNC16(sbase + SB_OFF + off, gB + goff);
        }
        CP_COMMIT();
    }

    // ---- warp layout: 4 (m) x 4 (n); warp tile 32 x 32 ----
    const int wm = wid >> 2, wn = wid & 3;

    float c[2][4][4];
    #pragma unroll
    for (int mi = 0; mi < 2; mi++)
        #pragma unroll
        for (int ni = 0; ni < 4; ni++)
            #pragma unroll
            for (int q = 0; q < 4; q++) c[mi][ni][q] = 0.f;

    // A frag base: lanes 0-15 -> rows (wm*32 + mi*16 + lane&15), lanes 16-31 -> +16B (k+8)
    const uint32_t aB = sbase + (uint32_t)(wm * 32 + (lane & 15)) * A_STRIDE
                      + ((uint32_t)(lane >> 4) << 4);
    // B frag base (non-trans x4, two n8-tiles per load):
    const uint32_t bOffBase = dup ? 0u : (uint32_t)SB_OFF;
    const uint32_t bB = sbase + bOffBase
                      + (uint32_t)(wn * 32 + (lane & 7) + ((lane >> 4) << 3)) * A_STRIDE
                      + (uint32_t)(((lane >> 3) & 1) << 4);

    CP_WAIT(1);            // chunk 0 resident
    __syncthreads();

    #pragma unroll
    for (int half = 0; half < 2; half++) {
        if (half == 1) {
            CP_WAIT(0);    // chunk 1 resident
            __syncthreads();
        }
        #pragma unroll
        for (int k8 = 0; k8 < 8; k8++) {
            const int ks = half * 8 + k8;
            uint32_t a[2][4];
            #pragma unroll
            for (int mi = 0; mi < 2; mi++)
                ldsm4(a[mi], aB + ks * 32 + mi * (16 * A_STRIDE));
            uint32_t b[2][4];   // b[p]: n8-tiles 2p, 2p+1; regs {t0k0,t0k8,t1k0,t1k8}
            #pragma unroll
            for (int p = 0; p < 2; p++)
                ldsm4(b[p], bB + ks * 32 + p * (16 * A_STRIDE));
            #pragma unroll
            for (int mi = 0; mi < 2; mi++)
                #pragma unroll
                for (int ni = 0; ni < 4; ni++)
                    mma16816(c[mi][ni], a[mi], &b[ni >> 1][(ni & 1) * 2]);
        }
    }
    __syncthreads();   // all smem reads done; safe to reuse smem as staging

    // ---- epilogue: direct store + transposed staging for the mirror tile ----
    const float thr = *thr_p, tt = *t_p;
    float cut2 = 3.0e38f;
    if (tt > 0.f) { float cd = 17.0f / tt - thr; cut2 = (cd > 0.f) ? cd * cd : -1.0f; }

    float* rs = reinterpret_cast<float*>(smem);     // [128 cols][RS_STRIDE]
    const bool mirror = !dup;
    const int gr = lane >> 2, gc = lane & 3;

    #pragma unroll
    for (int mi = 0; mi < 2; mi++) {
        const int lr0 = wm * 32 + mi * 16 + gr;
        const int r0 = row0 + lr0;
        const float sa0 = g_sq[r0], sa1 = g_sq[r0 + 8];
        #pragma unroll
        for (int ni = 0; ni < 4; ni++) {
            const int lc = wn * 32 + ni * 8 + gc * 2;
            const int col = col0 + lc;
            const float sb0 = g_sq[col], sb1 = g_sq[col + 1];
            float2 v0, v1;
            v0.x = epi(c[mi][ni][0], sa0, sb0, thr, tt, cut2);
            v0.y = epi(c[mi][ni][1], sa0, sb1, thr, tt, cut2);
            v1.x = epi(c[mi][ni][2], sa1, sb0, thr, tt, cut2);
            v1.y = epi(c[mi][ni][3], sa1, sb1, thr, tt, cut2);
            *reinterpret_cast<float2*>(out + (size_t)r0 * NN + col) = v0;
            *reinterpret_cast<float2*>(out + (size_t)(r0 + 8) * NN + col) = v1;
            if (mirror) {
                rs[(lc)     * RS_STRIDE + lr0]     = v0.x;
                rs[(lc + 1) * RS_STRIDE + lr0]     = v0.y;
                rs[(lc)     * RS_STRIDE + lr0 + 8] = v1.x;
                rs[(lc + 1) * RS_STRIDE + lr0 + 8] = v1.y;
            }
        }
    }

    if (mirror) {
        __syncthreads();
        #pragma unroll
        for (int it = 0; it < 8; it++) {
            int idx = tid + it * NT;            // 0..4095
            int j = idx >> 5, u = idx & 31;
            float4 v = *reinterpret_cast<const float4*>(&rs[j * RS_STRIDE + 4 * u]);
            *reinterpret_cast<float4*>(out + (size_t)(col0 + j) * NN + row0 + 4 * u) = v;
        }
    } else {
        // ---- fused diagonal-element fixup (verbatim R5 arithmetic) ----
        __syncthreads();   // order after this CTA's epilogue stores to the diagonal
        if (tid < 128) {
            const int i = row0 + tid;
            const float4* xr = reinterpret_cast<const float4*>(x + (size_t)i * DD);
            float dot = 0.f;
            #pragma unroll
            for (int u = 0; u < DD / 4; u++) {
                float4 v = xr[u];
                dot = fmaf(v.x, v.x, dot);
                dot = fmaf(v.y, v.y, dot);
                dot = fmaf(v.z, v.z, dot);
                dot = fmaf(v.w, v.w, dot);
            }
            float sq = g_sq[i];
            float d2 = fmaf(-2.f, dot, sq + sq);
            float dist = sqrtf(fmaxf(d2, 1e-12f));
            float v = 1.f - 1.f / (1.f + __expf(-(dist + thr) * tt));
            out[(size_t)i * NN + i] = v;
        }
    }
}

extern "C" void kernel_launch(void* const* d_in, const int* in_sizes, int n_in,
                              void* d_out, int out_size) {
    const float* x   = (const float*)d_in[0];
    const float* thr = (const float*)d_in[1];
    const float* t   = (const float*)d_in[2];
    float* out = (float*)d_out;

    cudaFuncSetAttribute(gemm_kernel, cudaFuncAttributeMaxDynamicSharedMemorySize, SM_TOTAL);

    prep_kernel<<<NN / 8, 256>>>(x);                      // sq norms + bf16 rows
    gemm_kernel<<<NPAIRS, NT, SM_TOTAL>>>(x, thr, t, out);  // triangle + mirror + diag
}

// round 8
// speedup vs baseline: 7.5022x; 1.2475x over previous
#include <cuda_runtime.h>
#include <cuda_bf16.h>
#include <math.h>
#include <cstdint>

#define NN 8192
#define DD 256

// ---------------- device scratch (no cudaMalloc allowed) ----------------
__device__ float g_sq[NN];
__device__ __nv_bfloat16 g_xb[(size_t)NN * DD];    // 4 MB bf16 copy of x   [row][k]

__device__ __forceinline__ uint32_t smem_u32(const void* p) {
    uint32_t a;
    asm("{ .reg .u64 t; cvta.to.shared.u64 t, %1; cvt.u32.u64 %0, t; }" : "=r"(a) : "l"(p));
    return a;
}

#define CP_ASYNC16(dst, src) \
    asm volatile("cp.async.cg.shared.global [%0], [%1], 16;" :: "r"(dst), "l"(src))
#define CP_COMMIT() asm volatile("cp.async.commit_group;" ::: "memory")
#define CP_WAIT(n)  asm volatile("cp.async.wait_group %0;" :: "n"(n) : "memory")

// ---------------- prep: sq norms + fp32 -> bf16 row-major copy ----------------
__global__ void prep_kernel(const float* __restrict__ x) {
    int warp = (blockIdx.x * blockDim.x + threadIdx.x) >> 5;
    int lane = threadIdx.x & 31;
    if (warp >= NN) return;
    const float4* xr = reinterpret_cast<const float4*>(x + (size_t)warp * DD);
    float4 a = xr[lane * 2];
    float4 b = xr[lane * 2 + 1];
    float s = a.x*a.x + a.y*a.y + a.z*a.z + a.w*a.w
            + b.x*b.x + b.y*b.y + b.z*b.z + b.w*b.w;
    #pragma unroll
    for (int o = 16; o; o >>= 1) s += __shfl_xor_sync(0xffffffffu, s, o);
    if (lane == 0) g_sq[warp] = s;

    __nv_bfloat162 p0 = __float22bfloat162_rn(make_float2(a.x, a.y));
    __nv_bfloat162 p1 = __float22bfloat162_rn(make_float2(a.z, a.w));
    __nv_bfloat162 p2 = __float22bfloat162_rn(make_float2(b.x, b.y));
    __nv_bfloat162 p3 = __float22bfloat162_rn(make_float2(b.z, b.w));
    uint4 v;
    v.x = *reinterpret_cast<uint32_t*>(&p0);
    v.y = *reinterpret_cast<uint32_t*>(&p1);
    v.z = *reinterpret_cast<uint32_t*>(&p2);
    v.w = *reinterpret_cast<uint32_t*>(&p3);
    reinterpret_cast<uint4*>(g_xb + (size_t)warp * DD)[lane] = v;
}

// ---------------- bf16 mma.sync GEMM, triangular tiles, 2-stage K-chunk pipeline ----------------
// K split into 4 chunks of 64 elems (128 B/row). Per chunk, A and B are
// [128 rows][144 B stride] (128 + 16 pad -> 4-bank rotation). 2 smem stages.
#define CH_BYTES  128                              // 64 bf16 per row-chunk
#define CH_STRIDE 144
#define TILE_B    (128 * CH_STRIDE)                // 18432
#define STAGE_B   (2 * TILE_B)                     // 36864 (A + B per stage)
#define SM_TOTAL  (2 * STAGE_B)                    // 73728
#define RS_STRIDE 132                              // staging: float[128][132] = 67584 <= 73728
#define NT 512                                     // 16 warps

__device__ __forceinline__ void ldsm4(uint32_t* r, uint32_t addr) {
    asm volatile("ldmatrix.sync.aligned.m8n8.x4.shared.b16 {%0,%1,%2,%3}, [%4];"
                 : "=r"(r[0]), "=r"(r[1]), "=r"(r[2]), "=r"(r[3]) : "r"(addr));
}
__device__ __forceinline__ void mma16816(float* c, const uint32_t* a, const uint32_t* b) {
    asm volatile("mma.sync.aligned.m16n8k16.row.col.f32.bf16.bf16.f32 "
                 "{%0,%1,%2,%3}, {%4,%5,%6,%7}, {%8,%9}, {%0,%1,%2,%3};"
                 : "+f"(c[0]), "+f"(c[1]), "+f"(c[2]), "+f"(c[3])
                 : "r"(a[0]), "r"(a[1]), "r"(a[2]), "r"(a[3]), "r"(b[0]), "r"(b[1]));
}

__device__ __forceinline__ float epi(float dot, float sa, float sb,
                                     float thr, float tt, float cut2) {
    float d2 = sa + sb - 2.f * dot;
    if (d2 > cut2) return 0.f;                    // 1-sigmoid saturates to exactly 0.0f
    float dist = sqrtf(fmaxf(d2, 1e-12f));
    return 1.f - 1.f / (1.f + __expf(-(dist + thr) * tt));
}

#define NTILE 64          // 8192 / 128
#define NPAIRS 2080       // 64*65/2 upper-triangle tiles (incl. diagonal)

__global__ void __launch_bounds__(NT, 2) gemm_kernel(
    const float* __restrict__ x,
    const float* __restrict__ thr_p, const float* __restrict__ t_p,
    float* __restrict__ out)
{
    extern __shared__ char smem[];
    const uint32_t sbase = smem_u32(smem);
    const int tid = threadIdx.x, wid = tid >> 5, lane = tid & 31;

    // triangular decode: block i -> (by, bx) with bx >= by
    int bi = blockIdx.x;
    int by = (int)(64.5f - sqrtf(64.5f * 64.5f - 2.0f * (float)bi));
    #define FROW(b) ((b) * NTILE - ((b) * ((b) - 1)) / 2)
    while (FROW(by + 1) <= bi) by++;
    while (FROW(by) > bi) by--;
    const int bx = by + (bi - FROW(by));
    const int row0 = by * 128;
    const int col0 = bx * 128;
    const bool dup = (bx == by);

    const char* gA = reinterpret_cast<const char*>(g_xb) + (size_t)row0 * 512;
    const char* gB = reinterpret_cast<const char*>(g_xb) + (size_t)col0 * 512;

    // per-thread load slots: 2 x 16B per tile per chunk (1024 16B units / 512 thr)
    const int lr = tid >> 3;            // 0..63   base row (also +64)
    const int lu = tid & 7;             // 16B unit within 128B chunk-row

    // issue one K-chunk (A + optionally B) into a stage buffer
    #define ISSUE_CHUNK(c, st) do {                                                  \
        uint32_t sOff = (uint32_t)((st) * STAGE_B + lr * CH_STRIDE + lu * 16);       \
        size_t   gOff = (size_t)lr * 512 + (size_t)(c) * CH_BYTES + lu * 16;         \
        CP_ASYNC16(sbase + sOff,                gA + gOff);                          \
        CP_ASYNC16(sbase + sOff + 64*CH_STRIDE, gA + gOff + (size_t)64*512);         \
        if (!dup) {                                                                  \
            CP_ASYNC16(sbase + sOff + TILE_B,                gB + gOff);             \
            CP_ASYNC16(sbase + sOff + TILE_B + 64*CH_STRIDE, gB + gOff + (size_t)64*512); \
        }                                                                            \
        CP_COMMIT();                                                                 \
    } while (0)

    ISSUE_CHUNK(0, 0);
    ISSUE_CHUNK(1, 1);

    // ---- warp layout: 4 (m) x 4 (n); warp tile 32 x 32 ----
    const int wm = wid >> 2, wn = wid & 3;

    float c[2][4][4];
    #pragma unroll
    for (int mi = 0; mi < 2; mi++)
        #pragma unroll
        for (int ni = 0; ni < 4; ni++)
            #pragma unroll
            for (int q = 0; q < 4; q++) c[mi][ni][q] = 0.f;

    // frag bases (stage-relative)
    const uint32_t aRel = (uint32_t)(wm * 32 + (lane & 15)) * CH_STRIDE
                        + ((uint32_t)(lane >> 4) << 4);
    const uint32_t bRel = (dup ? 0u : (uint32_t)TILE_B)
                        + (uint32_t)(wn * 32 + (lane & 7) + ((lane >> 4) << 3)) * CH_STRIDE
                        + (uint32_t)(((lane >> 3) & 1) << 4);

    #pragma unroll
    for (int ch = 0; ch < 4; ch++) {
        if (ch < 3) CP_WAIT(1); else CP_WAIT(0);
        __syncthreads();
        const uint32_t stg = sbase + (uint32_t)((ch & 1) * STAGE_B);
        #pragma unroll
        for (int ks = 0; ks < 4; ks++) {          // 4 k16-steps per 64-chunk
            uint32_t a[2][4];
            #pragma unroll
            for (int mi = 0; mi < 2; mi++)
                ldsm4(a[mi], stg + aRel + ks * 32 + mi * (16 * CH_STRIDE));
            uint32_t b[2][4];
            #pragma unroll
            for (int p = 0; p < 2; p++)
                ldsm4(b[p], stg + bRel + ks * 32 + p * (16 * CH_STRIDE));
            #pragma unroll
            for (int mi = 0; mi < 2; mi++)
                #pragma unroll
                for (int ni = 0; ni < 4; ni++)
                    mma16816(c[mi][ni], a[mi], &b[ni >> 1][(ni & 1) * 2]);
        }
        __syncthreads();
        if (ch + 2 < 4) ISSUE_CHUNK(ch + 2, ch & 1);
    }

    // ---- epilogue: direct store + transposed staging for the mirror tile ----
    const float thr = *thr_p, tt = *t_p;
    float cut2 = 3.0e38f;
    if (tt > 0.f) { float cd = 17.0f / tt - thr; cut2 = (cd > 0.f) ? cd * cd : -1.0f; }

    float* rs = reinterpret_cast<float*>(smem);     // [128 cols][RS_STRIDE]
    const bool mirror = !dup;
    const int gr = lane >> 2, gc = lane & 3;

    #pragma unroll
    for (int mi = 0; mi < 2; mi++) {
        const int lr0 = wm * 32 + mi * 16 + gr;
        const int r0 = row0 + lr0;
        const float sa0 = g_sq[r0], sa1 = g_sq[r0 + 8];
        #pragma unroll
        for (int ni = 0; ni < 4; ni++) {
            const int lc = wn * 32 + ni * 8 + gc * 2;
            const int col = col0 + lc;
            const float sb0 = g_sq[col], sb1 = g_sq[col + 1];
            float2 v0, v1;
            v0.x = epi(c[mi][ni][0], sa0, sb0, thr, tt, cut2);
            v0.y = epi(c[mi][ni][1], sa0, sb1, thr, tt, cut2);
            v1.x = epi(c[mi][ni][2], sa1, sb0, thr, tt, cut2);
            v1.y = epi(c[mi][ni][3], sa1, sb1, thr, tt, cut2);
            *reinterpret_cast<float2*>(out + (size_t)r0 * NN + col) = v0;
            *reinterpret_cast<float2*>(out + (size_t)(r0 + 8) * NN + col) = v1;
            if (mirror) {
                rs[(lc)     * RS_STRIDE + lr0]     = v0.x;
                rs[(lc + 1) * RS_STRIDE + lr0]     = v0.y;
                rs[(lc)     * RS_STRIDE + lr0 + 8] = v1.x;
                rs[(lc + 1) * RS_STRIDE + lr0 + 8] = v1.y;
            }
        }
    }

    if (mirror) {
        __syncthreads();
        #pragma unroll
        for (int it = 0; it < 8; it++) {
            int idx = tid + it * NT;            // 0..4095
            int j = idx >> 5, u = idx & 31;
            float4 v = *reinterpret_cast<const float4*>(&rs[j * RS_STRIDE + 4 * u]);
            *reinterpret_cast<float4*>(out + (size_t)(col0 + j) * NN + row0 + 4 * u) = v;
        }
    } else {
        // ---- fused diagonal-element fixup (verbatim R5 arithmetic) ----
        __syncthreads();   // order after this CTA's epilogue stores to the diagonal
        if (tid < 128) {
            const int i = row0 + tid;
            const float4* xr = reinterpret_cast<const float4*>(x + (size_t)i * DD);
            float dot = 0.f;
            #pragma unroll
            for (int u = 0; u < DD / 4; u++) {
                float4 v = xr[u];
                dot = fmaf(v.x, v.x, dot);
                dot = fmaf(v.y, v.y, dot);
                dot = fmaf(v.z, v.z, dot);
                dot = fmaf(v.w, v.w, dot);
            }
            float sq = g_sq[i];
            float d2 = fmaf(-2.f, dot, sq + sq);
            float dist = sqrtf(fmaxf(d2, 1e-12f));
            float v = 1.f - 1.f / (1.f + __expf(-(dist + thr) * tt));
            out[(size_t)i * NN + i] = v;
        }
    }
}

extern "C" void kernel_launch(void* const* d_in, const int* in_sizes, int n_in,
                              void* d_out, int out_size) {
    const float* x   = (const float*)d_in[0];
    const float* thr = (const float*)d_in[1];
    const float* t   = (const float*)d_in[2];
    float* out = (float*)d_out;

    cudaFuncSetAttribute(gemm_kernel, cudaFuncAttributeMaxDynamicSharedMemorySize, SM_TOTAL);

    prep_kernel<<<NN / 8, 256>>>(x);                      // sq norms + bf16 rows
    gemm_kernel<<<NPAIRS, NT, SM_TOTAL>>>(x, thr, t, out);  // triangle + mirror + diag
}